// round 16
// baseline (speedup 1.0000x reference)
#include <cuda_runtime.h>
#include <cuda_bf16.h>
#include <cstdint>

#define BATCH 1024
#define NIN   1152
#define DIN   8
#define NOUT  10
#define DOUT  16
#define QTOT  (NIN * DIN)        // 9216
#define NCHUNK 36
#define CI     (NIN / NCHUNK)    // 32 i per chunk

// ---------------- static device scratch ----------------
__device__ float g_partial[NCHUNK][BATCH][NOUT][DOUT];
__device__ float g_pden[NCHUNK][BATCH][NOUT];
__device__ float g_vsum[BATCH][NOUT][DOUT];
// pass-0 GEMM operands (k16, 2 i per slab) — proven R9
#define GSLABS_TOT (NIN / 2)
__device__ uint32_t g_xpair[GSLABS_TOT * BATCH * 8];
__device__ uint32_t g_Wbf[GSLABS_TOT * 160 * 8];
// passes 1-2: m16n8k8 fragments, hi/lo SPLIT arrays (layouts proven R12)
__device__ uint32_t g_Wh[NIN * NOUT * 64];
__device__ uint32_t g_Wl[NIN * NOUT * 64];
__device__ uint32_t g_xh[NIN * 64 * 64];
__device__ uint32_t g_xl[NIN * 64 * 64];

// ---------------- cp.async ----------------
__device__ __forceinline__ void cpa16(void* smem_dst, const void* gmem_src) {
    unsigned s = (unsigned)__cvta_generic_to_shared(smem_dst);
    asm volatile("cp.async.cg.shared.global [%0], [%1], 16;" :: "r"(s), "l"(gmem_src));
}
__device__ __forceinline__ void cpa_commit() { asm volatile("cp.async.commit_group;"); }
template <int N> __device__ __forceinline__ void cpa_wait() {
    asm volatile("cp.async.wait_group %0;" :: "n"(N));
}

// ---------------- mma helpers ----------------
__device__ __forceinline__ void hmma16816(float* c, uint32_t a0, uint32_t a1,
                                          uint32_t a2, uint32_t a3,
                                          uint32_t b0, uint32_t b1) {
    asm volatile(
        "mma.sync.aligned.m16n8k16.row.col.f32.bf16.bf16.f32 "
        "{%0,%1,%2,%3}, {%4,%5,%6,%7}, {%8,%9}, {%0,%1,%2,%3};"
        : "+f"(c[0]), "+f"(c[1]), "+f"(c[2]), "+f"(c[3])
        : "r"(a0), "r"(a1), "r"(a2), "r"(a3), "r"(b0), "r"(b1));
}
__device__ __forceinline__ void hmma1688(float* c, uint32_t a0, uint32_t a1, uint32_t b0) {
    asm volatile(
        "mma.sync.aligned.m16n8k8.row.col.f32.bf16.bf16.f32 "
        "{%0,%1,%2,%3}, {%4,%5}, {%6}, {%0,%1,%2,%3};"
        : "+f"(c[0]), "+f"(c[1]), "+f"(c[2]), "+f"(c[3])
        : "r"(a0), "r"(a1), "r"(b0));
}
__device__ __forceinline__ float ex2f(float x) {
    float r; asm("ex2.approx.f32 %0, %1;" : "=f"(r) : "f"(x)); return r;
}

__device__ __forceinline__ uint32_t pack_bf16(float f0, float f1) {
    __nv_bfloat162 h = __float22bfloat162_rn(make_float2(f0, f1));
    return *reinterpret_cast<uint32_t*>(&h);
}
__device__ __forceinline__ uint32_t pack_bf16_lo(float f0, float f1) {
    float h0 = __bfloat162float(__float2bfloat16_rn(f0));
    float h1 = __bfloat162float(__float2bfloat16_rn(f1));
    return pack_bf16(f0 - h0, f1 - h1);
}

// ---------------- fused prep: read x and W ONCE, write all operand layouts ----
// x-unit (i, b, ep): float2 -> hi (g_xh + g_xpair, identical values) + lo (g_xl)
// W-unit (in, d, ep): float2 -> hi (g_Wh + g_Wbf) + lo (g_Wl)
#define XF_BLOCKS 2304    // 1152*1024*4 / 2048
#define WF_BLOCKS 360     // 11520*16*4 / 2048
__global__ void prep(const float* __restrict__ x, const float* __restrict__ W)
{
    if (blockIdx.x < XF_BLOCKS) {
#pragma unroll
        for (int k = 0; k < 8; k++) {
            const int g = blockIdx.x * 2048 + k * 256 + threadIdx.x;
            const int ep = g & 3;
            const int b  = (g >> 2) & 1023;
            const int i  = g >> 12;
            const float2 v = *reinterpret_cast<const float2*>(
                x + (size_t)b * QTOT + i * 8 + ep * 2);
            const uint32_t hi = pack_bf16(v.x, v.y);
            const uint32_t lo = pack_bf16_lo(v.x, v.y);
            // route layout: t=b>>4, r=(b>>3)&1, gid=b&7, lane=gid*4+ep
            const int t = b >> 4, r = (b >> 3) & 1, gid = b & 7;
            const size_t ih = ((size_t)i * 64 + t) * 64 + (gid * 4 + ep) * 2 + r;
            g_xh[ih] = hi;
            g_xl[ih] = lo;
            // pass-0 layout: slab=i>>1, q=(i&1)|(ep<<1)
            const size_t ip = (((size_t)(i >> 1)) * 1024 + b) * 8 + ((i & 1) | (ep << 1));
            g_xpair[ip] = hi;
        }
    } else {
#pragma unroll
        for (int k = 0; k < 8; k++) {
            const int g = (blockIdx.x - XF_BLOCKS) * 2048 + k * 256 + threadIdx.x;
            const int ep = g & 3;
            const int d  = (g >> 2) & 15;
            const int in = g >> 6;                 // i*10 + n
            const float2 v = *reinterpret_cast<const float2*>(
                W + ((size_t)in * 16 + d) * 8 + ep * 2);
            const uint32_t hi = pack_bf16(v.x, v.y);
            const uint32_t lo = pack_bf16_lo(v.x, v.y);
            // route layout: lane=(d&7)*4+ep, r=d>>3
            const size_t iw = (size_t)in * 64 + (d & 7) * 8 + ep * 2 + (d >> 3);
            g_Wh[iw] = hi;
            g_Wl[iw] = lo;
            // pass-0 layout: slab=i>>1, nd=n*16+d, q=(i&1)|(ep<<1)
            const int i_ = in / 10, n_ = in % 10;
            const size_t ib = (((size_t)(i_ >> 1)) * 160 + n_ * 16 + d) * 8
                              + ((i_ & 1) | (ep << 1));
            g_Wbf[ib] = hi;
        }
    }
}

// ---------------- pass 0 (uniform weights) — proven R9 GEMM ----------------
__global__ void __launch_bounds__(128) gemm_pass0()
{
    const int warp = threadIdx.x >> 5;
    const int lane = threadIdx.x & 31;
    const int gid = lane >> 2;
    const int tig = lane & 3;
    const int chunk = blockIdx.x;
    const int brow = blockIdx.y * 64 + warp * 16;
    const int slab0 = chunk * 16;

    float acc[20][4];
#pragma unroll
    for (int t = 0; t < 20; t++)
#pragma unroll
        for (int k = 0; k < 4; k++) acc[t][k] = 0.0f;

    for (int s = 0; s < 16; s++) {
        const uint32_t* __restrict__ xa =
            g_xpair + ((size_t)(slab0 + s) * BATCH + brow) * 8;
        const uint2 alo = *reinterpret_cast<const uint2*>(xa + gid * 8 + tig * 2);
        const uint2 ahi = *reinterpret_cast<const uint2*>(xa + (gid + 8) * 8 + tig * 2);
        const uint32_t a0 = alo.x, a2 = alo.y, a1 = ahi.x, a3 = ahi.y;

        const uint32_t* __restrict__ wb = g_Wbf + (size_t)(slab0 + s) * 160 * 8;
#pragma unroll
        for (int t = 0; t < 20; t++) {
            const uint2 bb = *reinterpret_cast<const uint2*>(wb + (t * 8 + gid) * 8 + tig * 2);
            hmma16816(acc[t], a0, a1, a2, a3, bb.x, bb.y);
        }
    }

    float* base0 = &g_partial[chunk][brow + gid][0][0];
    float* base1 = &g_partial[chunk][brow + gid + 8][0][0];
#pragma unroll
    for (int t = 0; t < 20; t++) {
        const int nd = t * 8 + tig * 2;
        *reinterpret_cast<float2*>(base0 + nd) = make_float2(acc[t][0], acc[t][1]);
        *reinterpret_cast<float2*>(base1 + nd) = make_float2(acc[t][2], acc[t][3]);
    }
}

// ---------------- passes 1-2: transposed-MMA fused routing pass ----------------
// RSI=4 unroll; Xl (pass-2 only) read via coalesced LDG.64 -> smem 48KB, 4 CTAs/SM.
#define RSI 4
#define RNSUB (CI / RSI)                 // 8

template <bool PRECISE>
__device__ __forceinline__ void route_impl()
{
    constexpr int WHALF = RSI * NOUT * 64;              // 2560 u32 (hi part)
    constexpr int WSUB  = WHALF * (PRECISE ? 2 : 1);    // per-buffer u32
    extern __shared__ uint32_t smr[];
    uint32_t* ws  = smr;
    uint32_t* xsm = smr + 2 * WSUB;                     // x hi tile: 2048 u32

    const int tid  = threadIdx.x;
    const int n    = tid >> 5;
    const int lane = tid & 31;
    const int gid  = lane >> 2;
    const int tig  = lane & 3;
    const int chunk = blockIdx.x;
    const int i0    = chunk * CI;
    const int bt    = blockIdx.y;
    const int b0    = bt * 16;

    // stage x hi tile (512 uint4)
#pragma unroll
    for (int k = 0; k < 2; k++) {
        const int idx = tid + k * 320;
        if (idx < 512) {
            const int il = idx >> 4, off = idx & 15;
            cpa16(xsm + il * 64 + off * 4,
                  g_xh + ((size_t)(i0 + il) * 64 + bt) * 64 + off * 4);
        }
    }
    // stage W sub 0
#pragma unroll
    for (int k = 0; k < 2; k++) {
        const int idx = tid + k * 320;
        cpa16(ws + idx * 4, g_Wh + (size_t)i0 * 640 + idx * 4);
        if (PRECISE)
            cpa16(ws + WHALF + idx * 4, g_Wl + (size_t)i0 * 640 + idx * 4);
    }
    cpa_commit();

    const float L2E = 1.4426950408889634f;
    float V0[4], V1[4];
    {
        float2 va = *reinterpret_cast<const float2*>(&g_vsum[b0 + gid][n][2 * tig]);
        float2 vb = *reinterpret_cast<const float2*>(&g_vsum[b0 + gid][n][2 * tig + 8]);
        float2 vc = *reinterpret_cast<const float2*>(&g_vsum[b0 + gid + 8][n][2 * tig]);
        float2 vd = *reinterpret_cast<const float2*>(&g_vsum[b0 + gid + 8][n][2 * tig + 8]);
        V0[0] = va.x * L2E; V0[1] = va.y * L2E; V0[2] = vb.x * L2E; V0[3] = vb.y * L2E;
        V1[0] = vc.x * L2E; V1[1] = vc.y * L2E; V1[2] = vd.x * L2E; V1[3] = vd.y * L2E;
    }

    float s0[4] = {0, 0, 0, 0}, s1[4] = {0, 0, 0, 0};
    float den0 = 0.0f, den1 = 0.0f;

    for (int s = 0; s < RNSUB; s++) {
        if (s + 1 < RNSUB) {
            uint32_t* dst = ws + ((s + 1) & 1) * WSUB;
            const size_t srcoff = (size_t)(i0 + (s + 1) * RSI) * 640;
#pragma unroll
            for (int k = 0; k < 2; k++) {
                const int idx = tid + k * 320;
                cpa16(dst + idx * 4, g_Wh + srcoff + idx * 4);
                if (PRECISE)
                    cpa16(dst + WHALF + idx * 4, g_Wl + srcoff + idx * 4);
            }
            cpa_commit();
            cpa_wait<1>();
        } else {
            cpa_wait<0>();
        }
        __syncthreads();

        // hoisted row pointers: inner offsets are compile-time immediates
        const uint32_t* __restrict__ wrow = ws + (s & 1) * WSUB + n * 64 + lane * 2;
        const uint32_t* __restrict__ xrow = xsm + s * (RSI * 64) + lane * 2;
        // pass-2: Xl straight from global (coalesced LDG.64, L2-resident)
        const uint32_t* __restrict__ xlg = PRECISE
            ? g_xl + ((size_t)(i0 + s * RSI) * 64 + bt) * 64 + lane * 2
            : nullptr;

#pragma unroll
        for (int ii = 0; ii < RSI; ii++) {
            const uint2 Xh = *reinterpret_cast<const uint2*>(xrow + ii * 64);
            const uint2 Wh = *reinterpret_cast<const uint2*>(wrow + ii * (NOUT * 64));

            float u0[4] = {0, 0, 0, 0}, u1[4] = {0, 0, 0, 0};
            hmma1688(u0, Xh.x, Xh.y, Wh.x);     // hi*hi, d tile 0
            hmma1688(u1, Xh.x, Xh.y, Wh.y);     // hi*hi, d tile 1
            if (PRECISE) {
                const uint2 Xl = *reinterpret_cast<const uint2*>(xlg + ii * 4096);
                const uint2 Wl = *reinterpret_cast<const uint2*>(wrow + WHALF + ii * (NOUT * 64));
                // mixed term xh*wl + xl*wh in ONE k16 MMA per d-tile
                hmma16816(u0, Xh.x, Xh.y, Xl.x, Xl.y, Wl.x, Wh.x);
                hmma16816(u1, Xh.x, Xh.y, Xl.x, Xl.y, Wl.y, Wh.y);
            }

            float p0 = u0[0] * V0[0] + u0[1] * V0[1] + u1[0] * V0[2] + u1[1] * V0[3];
            float p1 = u0[2] * V1[0] + u0[3] * V1[1] + u1[2] * V1[2] + u1[3] * V1[3];
            p0 += __shfl_xor_sync(0xffffffffu, p0, 1);
            p0 += __shfl_xor_sync(0xffffffffu, p0, 2);
            p1 += __shfl_xor_sync(0xffffffffu, p1, 1);
            p1 += __shfl_xor_sync(0xffffffffu, p1, 2);
            const float w0 = ex2f(p0);   // logits O(10): no max-shift needed
            const float w1 = ex2f(p1);

            s0[0] += w0 * u0[0]; s0[1] += w0 * u0[1];
            s0[2] += w1 * u0[2]; s0[3] += w1 * u0[3];
            s1[0] += w0 * u1[0]; s1[1] += w0 * u1[1];
            s1[2] += w1 * u1[2]; s1[3] += w1 * u1[3];
            den0 += w0; den1 += w1;
        }
        __syncthreads();
    }

    *reinterpret_cast<float2*>(&g_partial[chunk][b0 + gid][n][2 * tig])         = make_float2(s0[0], s0[1]);
    *reinterpret_cast<float2*>(&g_partial[chunk][b0 + gid][n][2 * tig + 8])     = make_float2(s1[0], s1[1]);
    *reinterpret_cast<float2*>(&g_partial[chunk][b0 + gid + 8][n][2 * tig])     = make_float2(s0[2], s0[3]);
    *reinterpret_cast<float2*>(&g_partial[chunk][b0 + gid + 8][n][2 * tig + 8]) = make_float2(s1[2], s1[3]);
    if (tig == 0) {
        g_pden[chunk][b0 + gid][n]     = den0;
        g_pden[chunk][b0 + gid + 8][n] = den1;
    }
}

// pass 1 (bf16 steering) and pass 2 (bf16x3): both 4 CTAs/SM now
__global__ void __launch_bounds__(320, 4) route_pass1() { route_impl<false>(); }
__global__ void __launch_bounds__(320, 4) route_pass2() { route_impl<true>(); }

// ---------------- squash / vsum update ----------------
template <bool FIRST, bool LAST>
__global__ void __launch_bounds__(NOUT * DOUT)
squash_update(float* __restrict__ out)
{
    const int b = blockIdx.x;
    const int tid = threadIdx.x;
    const int n = tid >> 4;
    const int d = tid & 15;

    float num = 0.0f;
#pragma unroll
    for (int c = 0; c < NCHUNK; c++) num += g_partial[c][b][n][d];

    float den;
    if (FIRST) {
        den = (float)NIN;
    } else {
        den = 0.0f;
#pragma unroll
        for (int c = 0; c < NCHUNK; c++) den += g_pden[c][b][n];
    }

    const float s = num / den;

    float s2 = s * s;
#pragma unroll
    for (int off = 8; off; off >>= 1) s2 += __shfl_xor_sync(0xffffffffu, s2, off);

    const float scale = s2 / (1.0f + s2) * rsqrtf(s2 + 1e-7f);
    const float v = scale * s;

    if (LAST)       out[((size_t)b * NOUT + n) * DOUT + d] = v;
    else if (FIRST) g_vsum[b][n][d] = v;
    else            g_vsum[b][n][d] += v;
}

extern "C" void kernel_launch(void* const* d_in, const int* in_sizes, int n_in,
                              void* d_out, int out_size)
{
    const float* x;
    const float* W;
    if (in_sizes[0] == BATCH * NIN * DIN) { x = (const float*)d_in[0]; W = (const float*)d_in[1]; }
    else                                  { x = (const float*)d_in[1]; W = (const float*)d_in[0]; }
    float* out = (float*)d_out;

    constexpr int SM1 = (2 * 2560 + 2048) * 4;   // 28,672 B (pass 1)
    constexpr int SM2 = (2 * 5120 + 2048) * 4;   // 49,152 B = 48KB (pass 2)

    // smem opt-in (idempotent, host-side, graph-safe; proven R3-R7/R15)
    static bool attr_done = false;
    if (!attr_done) {
        cudaFuncSetAttribute(route_pass2, cudaFuncAttributeMaxDynamicSharedMemorySize, SM2);
        cudaFuncSetAttribute(route_pass1, cudaFuncAttributeMaxDynamicSharedMemorySize, SM1);
        attr_done = true;
    }

    prep<<<XF_BLOCKS + WF_BLOCKS, 256>>>(x, W);

    gemm_pass0<<<dim3(NCHUNK, BATCH / 64), 128>>>();
    squash_update<true , false><<<BATCH, NOUT * DOUT>>>(out);

    route_pass1<<<dim3(NCHUNK, BATCH / 16), 320, SM1>>>();
    squash_update<false, false><<<BATCH, NOUT * DOUT>>>(out);

    route_pass2<<<dim3(NCHUNK, BATCH / 16), 320, SM2>>>();
    squash_update<false, true ><<<BATCH, NOUT * DOUT>>>(out);
}

// round 17
// speedup vs baseline: 1.0930x; 1.0930x over previous
#include <cuda_runtime.h>
#include <cuda_bf16.h>
#include <cstdint>

#define BATCH 1024
#define NIN   1152
#define DIN   8
#define NOUT  10
#define DOUT  16
#define QTOT  (NIN * DIN)        // 9216
#define NCHUNK 36
#define CI     (NIN / NCHUNK)    // 32 i per chunk

// ---------------- static device scratch ----------------
__device__ float g_partial[NCHUNK][BATCH][NOUT][DOUT];
__device__ float g_pden[NCHUNK][BATCH][NOUT];
__device__ float g_vsum[BATCH][NOUT][DOUT];
// pass-0 GEMM operands (k16, 2 i per slab) — proven R9
#define GSLABS_TOT (NIN / 2)
__device__ uint32_t g_xpair[GSLABS_TOT * BATCH * 8];
__device__ uint32_t g_Wbf[GSLABS_TOT * 160 * 8];
// passes 1-2: m16n8k8 fragments, hi/lo SPLIT arrays (layouts proven R12)
__device__ uint32_t g_Wh[NIN * NOUT * 64];
__device__ uint32_t g_Wl[NIN * NOUT * 64];
__device__ uint32_t g_xh[NIN * 64 * 64];
__device__ uint32_t g_xl[NIN * 64 * 64];

// ---------------- cp.async ----------------
__device__ __forceinline__ void cpa16(void* smem_dst, const void* gmem_src) {
    unsigned s = (unsigned)__cvta_generic_to_shared(smem_dst);
    asm volatile("cp.async.cg.shared.global [%0], [%1], 16;" :: "r"(s), "l"(gmem_src));
}
__device__ __forceinline__ void cpa_commit() { asm volatile("cp.async.commit_group;"); }
template <int N> __device__ __forceinline__ void cpa_wait() {
    asm volatile("cp.async.wait_group %0;" :: "n"(N));
}

// ---------------- mma helpers ----------------
__device__ __forceinline__ void hmma16816(float* c, uint32_t a0, uint32_t a1,
                                          uint32_t a2, uint32_t a3,
                                          uint32_t b0, uint32_t b1) {
    asm volatile(
        "mma.sync.aligned.m16n8k16.row.col.f32.bf16.bf16.f32 "
        "{%0,%1,%2,%3}, {%4,%5,%6,%7}, {%8,%9}, {%0,%1,%2,%3};"
        : "+f"(c[0]), "+f"(c[1]), "+f"(c[2]), "+f"(c[3])
        : "r"(a0), "r"(a1), "r"(a2), "r"(a3), "r"(b0), "r"(b1));
}
__device__ __forceinline__ void hmma1688(float* c, uint32_t a0, uint32_t a1, uint32_t b0) {
    asm volatile(
        "mma.sync.aligned.m16n8k8.row.col.f32.bf16.bf16.f32 "
        "{%0,%1,%2,%3}, {%4,%5}, {%6}, {%0,%1,%2,%3};"
        : "+f"(c[0]), "+f"(c[1]), "+f"(c[2]), "+f"(c[3])
        : "r"(a0), "r"(a1), "r"(b0));
}
__device__ __forceinline__ float ex2f(float x) {
    float r; asm("ex2.approx.f32 %0, %1;" : "=f"(r) : "f"(x)); return r;
}

__device__ __forceinline__ uint32_t pack_bf16(float f0, float f1) {
    __nv_bfloat162 h = __float22bfloat162_rn(make_float2(f0, f1));
    return *reinterpret_cast<uint32_t*>(&h);
}
__device__ __forceinline__ uint32_t pack_bf16_lo(float f0, float f1) {
    float h0 = __bfloat162float(__float2bfloat16_rn(f0));
    float h1 = __bfloat162float(__float2bfloat16_rn(f1));
    return pack_bf16(f0 - h0, f1 - h1);
}

// ---------------- fused prep: read x and W ONCE, write all operand layouts ----
#define XF_BLOCKS 2304
#define WF_BLOCKS 360
__global__ void prep(const float* __restrict__ x, const float* __restrict__ W)
{
    if (blockIdx.x < XF_BLOCKS) {
#pragma unroll
        for (int k = 0; k < 8; k++) {
            const int g = blockIdx.x * 2048 + k * 256 + threadIdx.x;
            const int ep = g & 3;
            const int b  = (g >> 2) & 1023;
            const int i  = g >> 12;
            const float2 v = *reinterpret_cast<const float2*>(
                x + (size_t)b * QTOT + i * 8 + ep * 2);
            const uint32_t hi = pack_bf16(v.x, v.y);
            const uint32_t lo = pack_bf16_lo(v.x, v.y);
            // route layout: t=b>>4, r=(b>>3)&1, gid=b&7, lane=gid*4+ep
            const int t = b >> 4, r = (b >> 3) & 1, gid = b & 7;
            const size_t ih = ((size_t)i * 64 + t) * 64 + (gid * 4 + ep) * 2 + r;
            g_xh[ih] = hi;
            g_xl[ih] = lo;
            // pass-0 layout: slab=i>>1, q=(i&1)|(ep<<1)
            const size_t ip = (((size_t)(i >> 1)) * 1024 + b) * 8 + ((i & 1) | (ep << 1));
            g_xpair[ip] = hi;
        }
    } else {
#pragma unroll
        for (int k = 0; k < 8; k++) {
            const int g = (blockIdx.x - XF_BLOCKS) * 2048 + k * 256 + threadIdx.x;
            const int ep = g & 3;
            const int d  = (g >> 2) & 15;
            const int in = g >> 6;                 // i*10 + n
            const float2 v = *reinterpret_cast<const float2*>(
                W + ((size_t)in * 16 + d) * 8 + ep * 2);
            const uint32_t hi = pack_bf16(v.x, v.y);
            const uint32_t lo = pack_bf16_lo(v.x, v.y);
            // route layout: lane=(d&7)*4+ep, r=d>>3
            const size_t iw = (size_t)in * 64 + (d & 7) * 8 + ep * 2 + (d >> 3);
            g_Wh[iw] = hi;
            g_Wl[iw] = lo;
            // pass-0 layout
            const int i_ = in / 10, n_ = in % 10;
            const size_t ib = (((size_t)(i_ >> 1)) * 160 + n_ * 16 + d) * 8
                              + ((i_ & 1) | (ep << 1));
            g_Wbf[ib] = hi;
        }
    }
}

// ---------------- pass 0 (uniform weights) — proven R9 GEMM ----------------
__global__ void __launch_bounds__(128) gemm_pass0()
{
    const int warp = threadIdx.x >> 5;
    const int lane = threadIdx.x & 31;
    const int gid = lane >> 2;
    const int tig = lane & 3;
    const int chunk = blockIdx.x;
    const int brow = blockIdx.y * 64 + warp * 16;
    const int slab0 = chunk * 16;

    float acc[20][4];
#pragma unroll
    for (int t = 0; t < 20; t++)
#pragma unroll
        for (int k = 0; k < 4; k++) acc[t][k] = 0.0f;

    for (int s = 0; s < 16; s++) {
        const uint32_t* __restrict__ xa =
            g_xpair + ((size_t)(slab0 + s) * BATCH + brow) * 8;
        const uint2 alo = *reinterpret_cast<const uint2*>(xa + gid * 8 + tig * 2);
        const uint2 ahi = *reinterpret_cast<const uint2*>(xa + (gid + 8) * 8 + tig * 2);
        const uint32_t a0 = alo.x, a2 = alo.y, a1 = ahi.x, a3 = ahi.y;

        const uint32_t* __restrict__ wb = g_Wbf + (size_t)(slab0 + s) * 160 * 8;
#pragma unroll
        for (int t = 0; t < 20; t++) {
            const uint2 bb = *reinterpret_cast<const uint2*>(wb + (t * 8 + gid) * 8 + tig * 2);
            hmma16816(acc[t], a0, a1, a2, a3, bb.x, bb.y);
        }
    }

    float* base0 = &g_partial[chunk][brow + gid][0][0];
    float* base1 = &g_partial[chunk][brow + gid + 8][0][0];
#pragma unroll
    for (int t = 0; t < 20; t++) {
        const int nd = t * 8 + tig * 2;
        *reinterpret_cast<float2*>(base0 + nd) = make_float2(acc[t][0], acc[t][1]);
        *reinterpret_cast<float2*>(base1 + nd) = make_float2(acc[t][2], acc[t][3]);
    }
}

// ---------------- passes 1-2: transposed-MMA fused routing pass (R15 shape) ----
#define RSI 4
#define RNSUB (CI / RSI)                 // 8

template <bool PRECISE>
__device__ __forceinline__ void route_impl()
{
    constexpr int WHALF = RSI * NOUT * 64;              // 2560 u32 (hi part)
    constexpr int WSUB  = WHALF * (PRECISE ? 2 : 1);    // per-buffer u32
    constexpr int XSZ   = 2048 * (PRECISE ? 2 : 1);
    extern __shared__ uint32_t smr[];
    uint32_t* ws  = smr;
    uint32_t* xsm = smr + 2 * WSUB;

    const int tid  = threadIdx.x;
    const int n    = tid >> 5;
    const int lane = tid & 31;
    const int gid  = lane >> 2;
    const int tig  = lane & 3;
    const int chunk = blockIdx.x;
    const int i0    = chunk * CI;
    const int bt    = blockIdx.y;
    const int b0    = bt * 16;

    // stage x tile (hi, + lo if PRECISE) — both in smem (R15 shape)
#pragma unroll
    for (int k = 0; k < (PRECISE ? 4 : 2); k++) {
        const int idx = tid + k * 320;
        if (idx < XSZ / 4) {
            const int part = idx >> 9;
            const int r = idx & 511;
            const int il = r >> 4, off = r & 15;
            const uint32_t* src = (part ? g_xl : g_xh) +
                ((size_t)(i0 + il) * 64 + bt) * 64 + off * 4;
            cpa16(xsm + part * 2048 + il * 64 + off * 4, src);
        }
    }
    // stage W sub 0
#pragma unroll
    for (int k = 0; k < 2; k++) {
        const int idx = tid + k * 320;
        cpa16(ws + idx * 4, g_Wh + (size_t)i0 * 640 + idx * 4);
        if (PRECISE)
            cpa16(ws + WHALF + idx * 4, g_Wl + (size_t)i0 * 640 + idx * 4);
    }
    cpa_commit();

    const float L2E = 1.4426950408889634f;
    float V0[4], V1[4];
    {
        float2 va = *reinterpret_cast<const float2*>(&g_vsum[b0 + gid][n][2 * tig]);
        float2 vb = *reinterpret_cast<const float2*>(&g_vsum[b0 + gid][n][2 * tig + 8]);
        float2 vc = *reinterpret_cast<const float2*>(&g_vsum[b0 + gid + 8][n][2 * tig]);
        float2 vd = *reinterpret_cast<const float2*>(&g_vsum[b0 + gid + 8][n][2 * tig + 8]);
        V0[0] = va.x * L2E; V0[1] = va.y * L2E; V0[2] = vb.x * L2E; V0[3] = vb.y * L2E;
        V1[0] = vc.x * L2E; V1[1] = vc.y * L2E; V1[2] = vd.x * L2E; V1[3] = vd.y * L2E;
    }

    float s0[4] = {0, 0, 0, 0}, s1[4] = {0, 0, 0, 0};
    float den0 = 0.0f, den1 = 0.0f;

    for (int s = 0; s < RNSUB; s++) {
        if (s + 1 < RNSUB) {
            uint32_t* dst = ws + ((s + 1) & 1) * WSUB;
            const size_t srcoff = (size_t)(i0 + (s + 1) * RSI) * 640;
#pragma unroll
            for (int k = 0; k < 2; k++) {
                const int idx = tid + k * 320;
                cpa16(dst + idx * 4, g_Wh + srcoff + idx * 4);
                if (PRECISE)
                    cpa16(dst + WHALF + idx * 4, g_Wl + srcoff + idx * 4);
            }
            cpa_commit();
            cpa_wait<1>();
        } else {
            cpa_wait<0>();
        }
        __syncthreads();

        const uint32_t* __restrict__ wrow = ws + (s & 1) * WSUB + n * 64 + lane * 2;
        const uint32_t* __restrict__ xrow = xsm + s * (RSI * 64) + lane * 2;

#pragma unroll
        for (int ii = 0; ii < RSI; ii++) {
            const uint2 Xh = *reinterpret_cast<const uint2*>(xrow + ii * 64);
            const uint2 Wh = *reinterpret_cast<const uint2*>(wrow + ii * (NOUT * 64));

            float u0[4] = {0, 0, 0, 0}, u1[4] = {0, 0, 0, 0};
            hmma1688(u0, Xh.x, Xh.y, Wh.x);     // hi*hi, d tile 0
            hmma1688(u1, Xh.x, Xh.y, Wh.y);     // hi*hi, d tile 1
            if (PRECISE) {
                const uint2 Xl = *reinterpret_cast<const uint2*>(xrow + 2048 + ii * 64);
                const uint2 Wl = *reinterpret_cast<const uint2*>(wrow + WHALF + ii * (NOUT * 64));
                // mixed term xh*wl + xl*wh in ONE k16 MMA per d-tile
                hmma16816(u0, Xh.x, Xh.y, Xl.x, Xl.y, Wl.x, Wh.x);
                hmma16816(u1, Xh.x, Xh.y, Xl.x, Xl.y, Wl.y, Wh.y);
            }

            float p0 = u0[0] * V0[0] + u0[1] * V0[1] + u1[0] * V0[2] + u1[1] * V0[3];
            float p1 = u0[2] * V1[0] + u0[3] * V1[1] + u1[2] * V1[2] + u1[3] * V1[3];
            p0 += __shfl_xor_sync(0xffffffffu, p0, 1);
            p0 += __shfl_xor_sync(0xffffffffu, p0, 2);
            p1 += __shfl_xor_sync(0xffffffffu, p1, 1);
            p1 += __shfl_xor_sync(0xffffffffu, p1, 2);
            const float w0 = ex2f(p0);   // logits O(10): no max-shift needed
            const float w1 = ex2f(p1);

            s0[0] += w0 * u0[0]; s0[1] += w0 * u0[1];
            s0[2] += w1 * u0[2]; s0[3] += w1 * u0[3];
            s1[0] += w0 * u1[0]; s1[1] += w0 * u1[1];
            s1[2] += w1 * u1[2]; s1[3] += w1 * u1[3];
            den0 += w0; den1 += w1;
        }
        __syncthreads();
    }

    *reinterpret_cast<float2*>(&g_partial[chunk][b0 + gid][n][2 * tig])         = make_float2(s0[0], s0[1]);
    *reinterpret_cast<float2*>(&g_partial[chunk][b0 + gid][n][2 * tig + 8])     = make_float2(s1[0], s1[1]);
    *reinterpret_cast<float2*>(&g_partial[chunk][b0 + gid + 8][n][2 * tig])     = make_float2(s0[2], s0[3]);
    *reinterpret_cast<float2*>(&g_partial[chunk][b0 + gid + 8][n][2 * tig + 8]) = make_float2(s1[2], s1[3]);
    if (tig == 0) {
        g_pden[chunk][b0 + gid][n]     = den0;
        g_pden[chunk][b0 + gid + 8][n] = den1;
    }
}

// pass 1 (bf16 steering): 4 CTAs/SM; pass 2 (bf16x3): 3 CTAs/SM (R15 config)
__global__ void __launch_bounds__(320, 4) route_pass1() { route_impl<false>(); }
__global__ void __launch_bounds__(320, 3) route_pass2() { route_impl<true>(); }

// ---------------- squash / vsum update ----------------
template <bool FIRST, bool LAST>
__global__ void __launch_bounds__(NOUT * DOUT)
squash_update(float* __restrict__ out)
{
    const int b = blockIdx.x;
    const int tid = threadIdx.x;
    const int n = tid >> 4;
    const int d = tid & 15;

    float num = 0.0f;
#pragma unroll
    for (int c = 0; c < NCHUNK; c++) num += g_partial[c][b][n][d];

    float den;
    if (FIRST) {
        den = (float)NIN;
    } else {
        den = 0.0f;
#pragma unroll
        for (int c = 0; c < NCHUNK; c++) den += g_pden[c][b][n];
    }

    const float s = num / den;

    float s2 = s * s;
#pragma unroll
    for (int off = 8; off; off >>= 1) s2 += __shfl_xor_sync(0xffffffffu, s2, off);

    const float scale = s2 / (1.0f + s2) * rsqrtf(s2 + 1e-7f);
    const float v = scale * s;

    if (LAST)       out[((size_t)b * NOUT + n) * DOUT + d] = v;
    else if (FIRST) g_vsum[b][n][d] = v;
    else            g_vsum[b][n][d] += v;
}

extern "C" void kernel_launch(void* const* d_in, const int* in_sizes, int n_in,
                              void* d_out, int out_size)
{
    const float* x;
    const float* W;
    if (in_sizes[0] == BATCH * NIN * DIN) { x = (const float*)d_in[0]; W = (const float*)d_in[1]; }
    else                                  { x = (const float*)d_in[1]; W = (const float*)d_in[0]; }
    float* out = (float*)d_out;

    constexpr int SM1 = (2 * 2560 + 2048) * 4;   // 28,672 B (pass 1)
    constexpr int SM2 = (2 * 5120 + 4096) * 4;   // 57,344 B (pass 2, needs opt-in)

    // smem opt-in (idempotent, host-side, graph-safe; proven R3-R7/R15)
    static bool attr_done = false;
    if (!attr_done) {
        cudaFuncSetAttribute(route_pass2, cudaFuncAttributeMaxDynamicSharedMemorySize, SM2);
        cudaFuncSetAttribute(route_pass1, cudaFuncAttributeMaxDynamicSharedMemorySize, SM1);
        attr_done = true;
    }

    prep<<<XF_BLOCKS + WF_BLOCKS, 256>>>(x, W);

    gemm_pass0<<<dim3(NCHUNK, BATCH / 64), 128>>>();
    squash_update<true , false><<<BATCH, NOUT * DOUT>>>(out);

    route_pass1<<<dim3(NCHUNK, BATCH / 16), 320, SM1>>>();
    squash_update<false, false><<<BATCH, NOUT * DOUT>>>(out);

    route_pass2<<<dim3(NCHUNK, BATCH / 16), 320, SM2>>>();
    squash_update<false, true ><<<BATCH, NOUT * DOUT>>>(out);
}